// round 15
// baseline (speedup 1.0000x reference)
#include <cuda_runtime.h>

// Warp1DOp, direct gather, 2 px/thread.
// Both bilinear taps fetched with ONE aligned LDG.64 (float2 at e = c0 & ~1,
// clamped to [0, W-2]); a predicated scalar LDG covers the c1 == e+2 case
// (c0 odd && dx > 0, ~50% of lanes). This nearly halves gather L1tex
// wavefronts vs two scalar taps. Zeros padding via v0/v1 predication.
//   disp: __ldcs (streaming)    out: __stcs (evict-first)

#define N_ 4
#define C_ 32
#define H_ 384
#define W_ 1280
#define HW_ (H_ * W_)
#define CHW_ (C_ * HW_)
#define NHW_ (N_ * H_ * W_)
#define W2_ (W_ / 2)
#define NHW2_ (NHW_ / 2)

__global__ __launch_bounds__(256) void warp1d_kernel(
    const float* __restrict__ img,
    const float* __restrict__ disp,
    float* __restrict__ out)
{
    int t = blockIdx.x * blockDim.x + threadIdx.x;   // over N*H*W/2
    if (t >= NHW2_) return;

    int w2 = t % W2_;
    int nh = t / W2_;           // n*H + h
    int n  = nh / H_;
    int h  = nh % H_;
    int w  = w2 * 2;

    float2 d2 = __ldcs(reinterpret_cast<const float2*>(disp) + t);
    float dv[2] = {d2.x, d2.y};

    int   e[2], c1[2];
    bool  s0lo[2];              // tap0 is f2.x (c0 == e)
    bool  t1lo[2], t1hi[2];     // tap1 is f2.x / f2.y
    bool  v0[2], v1[2], xe[2];  // valid taps; extra load needed
    float dx[2], mdx[2];

#pragma unroll
    for (int i = 0; i < 2; ++i) {
        float x = (float)(w + i) - dv[i];
        x = fminf(fmaxf(x, -1.0f), (float)W_) + 1.0f;   // [0, W+1] padded coord
        float xf = floorf(x);
        int   p0 = (int)xf;
        float f  = x - xf;
        int   p1 = p0 + (f > 0.0f ? 1 : 0);             // == ceil(x)
        int  col0 = p0 - 1;                              // real img columns
        int  col1 = p1 - 1;
        v0[i] = ((unsigned)col0 < (unsigned)W_);
        v1[i] = ((unsigned)col1 < (unsigned)W_);
        int a = col0 & ~1;                               // aligned float2 base
        a = a < 0 ? 0 : a;
        a = a > (W_ - 2) ? (W_ - 2) : a;
        e[i]    = a;
        c1[i]   = col1;
        s0lo[i] = (col0 == a);
        t1lo[i] = (col1 == a);
        t1hi[i] = (col1 == a + 1);
        xe[i]   = (col1 == a + 2) && v1[i];              // needs extra scalar
        dx[i]   = f;
        mdx[i]  = 1.0f - f;
    }

    size_t base = (size_t)n * CHW_ + (size_t)h * W_;
    const float* __restrict__ irow = img + base;
    float* __restrict__ orow = out + base + w;

#pragma unroll 8
    for (int c = 0; c < C_; ++c) {
        const float* r = irow + (size_t)c * HW_;
        float2 o;
        float* op = &o.x;
#pragma unroll
        for (int i = 0; i < 2; ++i) {
            float2 f2 = __ldg(reinterpret_cast<const float2*>(r + e[i]));
            float ex = xe[i] ? __ldg(r + c1[i]) : 0.0f;   // predicated, in-bounds
            float t0 = s0lo[i] ? f2.x : f2.y;
            t0 = v0[i] ? t0 : 0.0f;
            float t1 = t1lo[i] ? f2.x : (t1hi[i] ? f2.y : ex);
            t1 = v1[i] ? t1 : 0.0f;
            op[i] = mdx[i] * t0 + dx[i] * t1;
        }
        __stcs(reinterpret_cast<float2*>(orow + (size_t)c * HW_), o);
    }
}

extern "C" void kernel_launch(void* const* d_in, const int* in_sizes, int n_in,
                              void* d_out, int out_size)
{
    const float* img  = (const float*)d_in[0];
    const float* disp = (const float*)d_in[1];
    float* out = (float*)d_out;

    const int threads = 256;
    const int blocks  = (NHW2_ + threads - 1) / threads;
    warp1d_kernel<<<blocks, threads>>>(img, disp, out);
}

// round 16
// speedup vs baseline: 1.4794x; 1.4794x over previous
#include <cuda_runtime.h>

// Warp1DOp, direct scalar gather, 4 px/thread — consolidated best variant.
// Established over R3..R15: the kernel is pinned at ~5.25 TB/s by the
// interleaved gather-read + stream-write DRAM mix; scalar predicated gathers
// are optimal (divergent wide loads pay per-lane-sector wavefronts and lose).
//   disp: LDG.128 __ldcs (streaming, zero reuse)
//   img : scalar __ldg gathers (cross-warp L1/L2 reuse)
//   out : STG.128 coalesced
// Grid divides exactly (NHW/4 = 491520 = 1920*256): no bounds guard.
// Interp as a + dx*(b-a): FADD+FFMA, no (1-dx) register set.

#define N_ 4
#define C_ 32
#define H_ 384
#define W_ 1280
#define HW_ (H_ * W_)
#define CHW_ (C_ * HW_)
#define NHW_ (N_ * H_ * W_)
#define W4_ (W_ / 4)
#define NHW4_ (NHW_ / 4)

__global__ __launch_bounds__(256) void warp1d_kernel(
    const float* __restrict__ img,
    const float* __restrict__ disp,
    float* __restrict__ out)
{
    const int t = blockIdx.x * blockDim.x + threadIdx.x;   // over N*H*W/4, exact

    const int w4 = t % W4_;
    const int nh = t / W4_;          // n*H + h
    const int w  = w4 * 4;

    float4 d4 = __ldcs(reinterpret_cast<const float4*>(disp) + t);
    const float dv[4] = {d4.x, d4.y, d4.z, d4.w};

    int   c0[4], c1[4];
    float dx[4];
    bool  v0[4], v1[4];

#pragma unroll
    for (int i = 0; i < 4; ++i) {
        float x = (float)(w + i) - dv[i];
        x = fminf(fmaxf(x, -1.0f), (float)W_) + 1.0f;   // [0, W+1] padded coord
        float xf = floorf(x);
        int   p0 = (int)xf;
        float f  = x - xf;
        c0[i] = p0 - 1;                                  // real img column
        c1[i] = c0[i] + (f > 0.0f ? 1 : 0);              // == ceil(x) - 1
        v0[i] = ((unsigned)c0[i] < (unsigned)W_);
        v1[i] = ((unsigned)c1[i] < (unsigned)W_);
        dx[i] = f;
    }

    const size_t base = (size_t)(nh / H_) * CHW_ + (size_t)(nh % H_) * W_;
    const float* __restrict__ irow = img + base;
    float* __restrict__ orow = out + base + w;

#pragma unroll 8
    for (int c = 0; c < C_; ++c) {
        const float* r = irow + (size_t)c * HW_;
        float a0 = v0[0] ? __ldg(r + c0[0]) : 0.0f;
        float b0 = v1[0] ? __ldg(r + c1[0]) : 0.0f;
        float a1 = v0[1] ? __ldg(r + c0[1]) : 0.0f;
        float b1 = v1[1] ? __ldg(r + c1[1]) : 0.0f;
        float a2 = v0[2] ? __ldg(r + c0[2]) : 0.0f;
        float b2 = v1[2] ? __ldg(r + c1[2]) : 0.0f;
        float a3 = v0[3] ? __ldg(r + c0[3]) : 0.0f;
        float b3 = v1[3] ? __ldg(r + c1[3]) : 0.0f;

        float4 o;
        o.x = fmaf(dx[0], b0 - a0, a0);
        o.y = fmaf(dx[1], b1 - a1, a1);
        o.z = fmaf(dx[2], b2 - a2, a2);
        o.w = fmaf(dx[3], b3 - a3, a3);
        __stcs(reinterpret_cast<float4*>(orow + (size_t)c * HW_), o);
    }
}

extern "C" void kernel_launch(void* const* d_in, const int* in_sizes, int n_in,
                              void* d_out, int out_size)
{
    const float* img  = (const float*)d_in[0];
    const float* disp = (const float*)d_in[1];
    float* out = (float*)d_out;

    warp1d_kernel<<<NHW4_ / 256, 256>>>(img, disp, out);
}

// round 17
// speedup vs baseline: 1.5744x; 1.0642x over previous
#include <cuda_runtime.h>

// Warp1DOp, 4 pixels per thread (float4 disp load + float4 store).
// out[n,c,h,w] = (1-dx)*imgp[x0] + dx*imgp[x1], x = clip(w - disp, -1, W) + 1,
// zeros padding (padded cols 0 and W+1).
//
// FINAL (reverted to R4 exactly — best measured variant, 88.6us kernel,
// 5.25 TB/s). R5..R16 falsified: smem staging (occ-serialized or
// crossbar-bound), divergent wide-load tap merges (per-lane-sector wavefront
// blowup), cache-policy hints (neutral), deeper unroll / fma-form interp
// (regressed codegen). The op is pinned at the DRAM throughput achievable
// for an interleaved gather-read + streaming-write mix.

#define N_ 4
#define C_ 32
#define H_ 384
#define W_ 1280
#define HW_ (H_ * W_)
#define CHW_ (C_ * HW_)
#define NHW_ (N_ * H_ * W_)
#define W4_ (W_ / 4)
#define NHW4_ (NHW_ / 4)

__global__ __launch_bounds__(256) void warp1d_kernel(
    const float* __restrict__ img,
    const float* __restrict__ disp,
    float* __restrict__ out)
{
    int t = blockIdx.x * blockDim.x + threadIdx.x;   // over N*H*W/4
    if (t >= NHW4_) return;

    int w4 = t % W4_;
    int nh = t / W4_;           // n*H + h
    int n  = nh / H_;
    int h  = nh % H_;
    int w  = w4 * 4;

    float4 d4 = reinterpret_cast<const float4*>(disp)[t];
    float dv[4] = {d4.x, d4.y, d4.z, d4.w};

    int   c0[4], c1[4];
    float dx[4], mdx[4];
    bool  v0[4], v1[4];

#pragma unroll
    for (int i = 0; i < 4; ++i) {
        float x = (float)(w + i) - dv[i];
        x = fminf(fmaxf(x, -1.0f), (float)W_) + 1.0f;   // [0, W+1] padded coord
        float xf = floorf(x);
        int   p0 = (int)xf;
        float f  = x - xf;
        int   p1 = p0 + (f > 0.0f ? 1 : 0);             // == ceil(x)
        c0[i] = p0 - 1;                                  // real img column
        c1[i] = p1 - 1;
        v0[i] = ((unsigned)c0[i] < (unsigned)W_);
        v1[i] = ((unsigned)c1[i] < (unsigned)W_);
        dx[i]  = f;
        mdx[i] = 1.0f - f;
    }

    size_t base = (size_t)n * CHW_ + (size_t)h * W_;
    const float* __restrict__ irow = img + base;
    float* __restrict__ orow = out + base + w;

#pragma unroll 4
    for (int c = 0; c < C_; ++c) {
        const float* r = irow + (size_t)c * HW_;
        float a0 = v0[0] ? __ldg(r + c0[0]) : 0.0f;
        float b0 = v1[0] ? __ldg(r + c1[0]) : 0.0f;
        float a1 = v0[1] ? __ldg(r + c0[1]) : 0.0f;
        float b1 = v1[1] ? __ldg(r + c1[1]) : 0.0f;
        float a2 = v0[2] ? __ldg(r + c0[2]) : 0.0f;
        float b2 = v1[2] ? __ldg(r + c1[2]) : 0.0f;
        float a3 = v0[3] ? __ldg(r + c0[3]) : 0.0f;
        float b3 = v1[3] ? __ldg(r + c1[3]) : 0.0f;

        float4 o;
        o.x = mdx[0] * a0 + dx[0] * b0;
        o.y = mdx[1] * a1 + dx[1] * b1;
        o.z = mdx[2] * a2 + dx[2] * b2;
        o.w = mdx[3] * a3 + dx[3] * b3;
        *reinterpret_cast<float4*>(orow + (size_t)c * HW_) = o;
    }
}

extern "C" void kernel_launch(void* const* d_in, const int* in_sizes, int n_in,
                              void* d_out, int out_size)
{
    const float* img  = (const float*)d_in[0];
    const float* disp = (const float*)d_in[1];
    float* out = (float*)d_out;

    const int threads = 256;
    const int blocks  = (NHW4_ + threads - 1) / threads;
    warp1d_kernel<<<blocks, threads>>>(img, disp, out);
}